// round 9
// baseline (speedup 1.0000x reference)
#include <cuda_runtime.h>
#include <cuda_bf16.h>
#include <cstdint>

// ---------------------------------------------------------------------------
// DifferentialDropout: x [64, D], noise [64, D]  (D = 512*28*28 = 401408)
//   1. gram_stats: 4-stage cp.async pipeline (f32 tiles -> smem), convert to
//      swizzled bf16 + stats, 16-warp k-quartered bf16 mma. Last block runs
//      the finalize (factors -> p) in-kernel.
//   2. dropout: out = noise >= p ? x/(1-p) : 0; block 0 re-zeroes scratch
//      for the next graph replay (initial state is .bss-zero).
// ---------------------------------------------------------------------------

static __device__ float        g_S[64];
static __device__ float        g_G[64 * 64];
static __device__ unsigned int g_maskw[64 * 32];   // 1024 bins per row
static __device__ float        g_p;
static __device__ unsigned int g_done;

#define KTILE   128
#define STAGES  4
#define F32_STAGE_WORDS 8192                    // 64 rows * 128 f32
#define SMEM_F32_U32    (STAGES * F32_STAGE_WORDS)
#define SMEM_BYTES      (STAGES * 32768 + 2 * 16384)   // 160 KB

// bf16 tile swizzle: 64 rows x 64 u32 words; 16B chunk c of row r at c^(r&7)
__device__ __forceinline__ int swz(int r, int w) {
    return (r << 6) + ((((w >> 2) ^ (r & 7)) << 2) | (w & 3));
}

__device__ __forceinline__ void cp_async16(uint32_t saddr, const void* gptr) {
    asm volatile("cp.async.cg.shared.global [%0], [%1], 16;"
                 :: "r"(saddr), "l"(gptr));
}
__device__ __forceinline__ void cp_commit() {
    asm volatile("cp.async.commit_group;");
}
template <int Nn> __device__ __forceinline__ void cp_wait() {
    asm volatile("cp.async.wait_group %0;" :: "n"(Nn));
}

// ------------------- fused stats + bf16 Gram + finalize --------------------
__global__ __launch_bounds__(512, 1)
void gram_stats_kernel(const float* __restrict__ x,
                       const float* __restrict__ noise,
                       float* __restrict__ out,
                       long long N, long long out_size,
                       int D, int ntiles) {
    extern __shared__ uint32_t dynsmem[];
    float*    fst = reinterpret_cast<float*>(dynsmem);        // 4 x 32KB
    uint32_t* bb  = dynsmem + SMEM_F32_U32;                   // 2 x 16KB

    __shared__ int sh_last;

    const int tid  = threadIdx.x;
    const int lane = tid & 31;
    const int warp = tid >> 5;

    // convert mapping: 8 threads/row, 4 float4 per thread
    const int lrow = tid >> 3;     // 0..63
    const int lc   = tid & 7;      // 0..7

    // mma mapping: 16 warps = (ib, jb, kq); 32x32 G tile over quarter-k
    const int kq = warp & 3;
    const int jb = (warp >> 2) & 1;
    const int ib = (warp >> 3) & 1;
    const int i0 = ib << 5;
    const int j0 = jb << 5;
    const int lrf = lane & 15;
    const int lch = lane >> 4;

    const uint32_t sb_f = (uint32_t)__cvta_generic_to_shared(fst);
    const uint32_t sb_b = (uint32_t)__cvta_generic_to_shared(bb);

    float acc[2][4][4];
    #pragma unroll
    for (int h = 0; h < 2; ++h)
        #pragma unroll
        for (int t = 0; t < 4; ++t)
            #pragma unroll
            for (int r = 0; r < 4; ++r) acc[h][t][r] = 0.f;

    float rsum = 0.f;
    unsigned long long rmask = 0ull;

    // issue one tile's loads into stage s (guarded), always commit
    auto issue = [&](int t, int s) {
        if (t < ntiles) {
            const float* base = x + (size_t)t * KTILE;
            #pragma unroll
            for (int j = 0; j < 4; ++j) {
                const int c = (j << 9) + tid;     // 0..2047 16B chunks
                const int row = c >> 5, col16 = c & 31;
                cp_async16(sb_f + (uint32_t)(s * 32768 + ((row << 5) + col16) * 16),
                           base + (size_t)row * D + (col16 << 2));
            }
        }
        cp_commit();
    };

    // prologue: fill stages 0..STAGES-2
    #pragma unroll
    for (int s = 0; s < STAGES - 1; ++s)
        issue(blockIdx.x + s * gridDim.x, s);

    int stage = 0, buf = 0;
    for (int t = blockIdx.x; t < ntiles; t += gridDim.x) {
        cp_wait<STAGES - 2>();
        __syncthreads();                       // stage `stage` ready for all

        // ---- convert + stats: f32 smem -> bf16 smem ----
        const float*  fs   = fst + stage * F32_STAGE_WORDS + (lrow << 7);
        uint32_t*     bbuf = bb + buf * 4096;
        #pragma unroll
        for (int i = 0; i < 4; ++i) {
            const int j4 = (i << 3) + lc;
            const float4 vv = *reinterpret_cast<const float4*>(fs + (j4 << 2));
            rsum += (vv.x + vv.y) + (vv.z + vv.w);
            float vals[4] = {vv.x, vv.y, vv.z, vv.w};
            #pragma unroll
            for (int e = 0; e < 4; ++e) {
                int b = __float2int_rn(vals[e]);           // == jnp.round
                if ((unsigned)(b + 32) < 64u) {
                    rmask |= 1ull << (b + 32);
                } else {                                   // never for N(0,1)
                    int wb = b + 512;
                    wb = wb < 0 ? 0 : (wb > 1023 ? 1023 : wb);
                    atomicOr(&g_maskw[(lrow << 5) + (wb >> 5)], 1u << (wb & 31));
                }
            }
            __nv_bfloat162 p0 = __floats2bfloat162_rn(vv.x, vv.y);
            __nv_bfloat162 p1 = __floats2bfloat162_rn(vv.z, vv.w);
            uint2 pk;
            pk.x = *reinterpret_cast<uint32_t*>(&p0);
            pk.y = *reinterpret_cast<uint32_t*>(&p1);
            *reinterpret_cast<uint2*>(&bbuf[swz(lrow, j4 << 1)]) = pk;
        }
        __syncthreads();                       // bf16 tile done

        // FIX: refill the stage 3 ahead in the ring: stage (stage+3)&3 was
        // consumed at the previous iteration (or is the still-empty S3 at
        // iter 0). The old code refilled `stage` itself, leaving S3 garbage
        // and shifting every subsequent tile by one ring slot.
        issue(t + (STAGES - 1) * gridDim.x, (stage + STAGES - 1) & (STAGES - 1));

        // ---- mma on bbuf: this warp's k-quarter (2 ks of 16) ----
        const uint32_t bufb = sb_b + (uint32_t)(buf * 16384);
        #pragma unroll
        for (int s = 0; s < 2; ++s) {
            const int cb = (kq << 2) + (s << 1);
            uint32_t a[2][4], bfr[2][4];
            #pragma unroll
            for (int h = 0; h < 2; ++h) {
                int r = i0 + (h << 4) + lrf;
                uint32_t addr = bufb + (uint32_t)((r << 8) + (((cb + lch) ^ (r & 7)) << 4));
                asm volatile("ldmatrix.sync.aligned.m8n8.x4.shared.b16 {%0,%1,%2,%3}, [%4];"
                             : "=r"(a[h][0]), "=r"(a[h][1]), "=r"(a[h][2]), "=r"(a[h][3])
                             : "r"(addr));
            }
            #pragma unroll
            for (int g = 0; g < 2; ++g) {
                int r = j0 + (g << 4) + lrf;
                uint32_t addr = bufb + (uint32_t)((r << 8) + (((cb + lch) ^ (r & 7)) << 4));
                asm volatile("ldmatrix.sync.aligned.m8n8.x4.shared.b16 {%0,%1,%2,%3}, [%4];"
                             : "=r"(bfr[g][0]), "=r"(bfr[g][1]), "=r"(bfr[g][2]), "=r"(bfr[g][3])
                             : "r"(addr));
            }
            #pragma unroll
            for (int h = 0; h < 2; ++h)
                #pragma unroll
                for (int g = 0; g < 2; ++g)
                    #pragma unroll
                    for (int f = 0; f < 2; ++f) {
                        const int nt = (g << 1) + f;
                        asm volatile("mma.sync.aligned.m16n8k16.row.col.f32.bf16.bf16.f32 "
                                     "{%0,%1,%2,%3}, {%4,%5,%6,%7}, {%8,%9}, {%0,%1,%2,%3};"
                                     : "+f"(acc[h][nt][0]), "+f"(acc[h][nt][1]),
                                       "+f"(acc[h][nt][2]), "+f"(acc[h][nt][3])
                                     : "r"(a[h][0]), "r"(a[h][1]), "r"(a[h][2]), "r"(a[h][3]),
                                       "r"(bfr[g][f]), "r"(bfr[g][f + 2]));
                    }
        }
        stage = (stage + 1) & (STAGES - 1);
        buf ^= 1;
    }
    cp_wait<0>();

    // ---- per-row stats reduce (8 adjacent lanes per row) ----
    rsum += __shfl_xor_sync(0xffffffffu, rsum, 1);
    rsum += __shfl_xor_sync(0xffffffffu, rsum, 2);
    rsum += __shfl_xor_sync(0xffffffffu, rsum, 4);
    rmask |= __shfl_xor_sync(0xffffffffu, rmask, 1);
    rmask |= __shfl_xor_sync(0xffffffffu, rmask, 2);
    rmask |= __shfl_xor_sync(0xffffffffu, rmask, 4);
    if (lc == 0) {
        atomicAdd(&g_S[lrow], rsum);
        atomicOr(&g_maskw[(lrow << 5) + 15], (uint32_t)(rmask & 0xffffffffull));
        atomicOr(&g_maskw[(lrow << 5) + 16], (uint32_t)(rmask >> 32));
    }

    // ---- merge 4 k-quarters in smem (reuse f32 stages), REDG once ----
    __syncthreads();
    float* mg = fst;                          // 3 x 16KB partials
    const int orow = lane >> 2;
    const int ocol = (lane & 3) << 1;
    if (kq > 0) {
        float* m = mg + (kq - 1) * 4096;
        #pragma unroll
        for (int h = 0; h < 2; ++h)
            #pragma unroll
            for (int g = 0; g < 2; ++g)
                #pragma unroll
                for (int f = 0; f < 2; ++f) {
                    const int nt = (g << 1) + f;
                    const int oi = i0 + (h << 4) + orow;
                    const int oj = j0 + (g << 4) + (f << 3) + ocol;
                    m[oi * 64 + oj]           = acc[h][nt][0];
                    m[oi * 64 + oj + 1]       = acc[h][nt][1];
                    m[(oi + 8) * 64 + oj]     = acc[h][nt][2];
                    m[(oi + 8) * 64 + oj + 1] = acc[h][nt][3];
                }
    }
    __syncthreads();
    if (kq == 0) {
        #pragma unroll
        for (int h = 0; h < 2; ++h)
            #pragma unroll
            for (int g = 0; g < 2; ++g)
                #pragma unroll
                for (int f = 0; f < 2; ++f) {
                    const int nt = (g << 1) + f;
                    const int oi = i0 + (h << 4) + orow;
                    const int oj = j0 + (g << 4) + (f << 3) + ocol;
                    const int e00 = oi * 64 + oj;
                    const int e10 = (oi + 8) * 64 + oj;
                    atomicAdd(&g_G[e00],
                              acc[h][nt][0] + mg[e00] + mg[4096 + e00] + mg[8192 + e00]);
                    atomicAdd(&g_G[e00 + 1],
                              acc[h][nt][1] + mg[e00 + 1] + mg[4096 + e00 + 1] + mg[8192 + e00 + 1]);
                    atomicAdd(&g_G[e10],
                              acc[h][nt][2] + mg[e10] + mg[4096 + e10] + mg[8192 + e10]);
                    atomicAdd(&g_G[e10 + 1],
                              acc[h][nt][3] + mg[e10 + 1] + mg[4096 + e10 + 1] + mg[8192 + e10 + 1]);
                }
    }

    // ---- last block runs finalize ----
    __threadfence();
    __syncthreads();
    if (tid == 0) {
        unsigned v = atomicAdd(&g_done, 1u);
        sh_last = (v == gridDim.x - 1) ? 1 : 0;
    }
    __syncthreads();
    if (!sh_last) return;
    __threadfence();

    {
        __shared__ double       sh_S[64], sh_inv[64], sh_R[64], sh_mse[64];
        __shared__ int          sh_pu[64];
        __shared__ unsigned int sh_orw[32];
        __shared__ float        sh_cand[64];

        const int row = (tid >> 2) & 63;
        const int q   = tid & 3;
        const double Dd     = (double)D;
        const double invD   = 1.0 / Dd;
        const double invDm1 = 1.0 / (Dd - 1.0);

        if (tid < 32) sh_orw[tid] = 0u;
        __syncthreads();

        if (tid < 256) {
            double R = 0.0;
            #pragma unroll
            for (int j = 0; j < 16; ++j) R += (double)g_G[row * 64 + (q << 4) + j];
            R += __shfl_xor_sync(0xffffffffu, R, 1);
            R += __shfl_xor_sync(0xffffffffu, R, 2);

            int pu = 0;
            #pragma unroll
            for (int w = 0; w < 8; ++w) {
                unsigned m = g_maskw[row * 32 + (q << 3) + w];
                pu += __popc(m);
                atomicOr(&sh_orw[(q << 3) + w], m);
            }
            pu += __shfl_xor_sync(0xffffffffu, pu, 1);
            pu += __shfl_xor_sync(0xffffffffu, pu, 2);

            if (q == 0) {
                sh_R[row]  = R;
                sh_pu[row] = pu;
                sh_S[row]  = (double)g_S[row];
            }
        }
        __syncthreads();

        if (tid < 64) {
            double Si = sh_S[tid];
            double covii = ((double)g_G[tid * 64 + tid] - Si * Si * invD) * invDm1;
            sh_inv[tid] = 1.0 / sqrt(covii);
            double T = 0.0;
            for (int j = 0; j < 64; ++j) T += sh_R[j];
            sh_mse[tid] = ((double)g_G[tid * 64 + tid]
                           - 2.0 * sh_R[tid] / 64.0 + T / 4096.0) * invD;
        }
        __syncthreads();

        if (tid < 256) {
            const double Si  = sh_S[row];
            const double ivi = sh_inv[row];
            double f1 = 0.0;
            #pragma unroll
            for (int j = 0; j < 16; ++j) {
                const int jj = (q << 4) + j;
                double cov = ((double)g_G[row * 64 + jj] - Si * sh_S[jj] * invD) * invDm1;
                double c = cov * ivi * sh_inv[jj];
                c = fmin(fmax(c, -1.0), 1.0);
                f1 += fabs(c);
            }
            f1 += __shfl_xor_sync(0xffffffffu, f1, 1);
            f1 += __shfl_xor_sync(0xffffffffu, f1, 2);

            if (q == 0) {
                double tot = 0.0;
                for (int j = 0; j < 64; ++j) tot += sh_mse[j];
                int tu = 0;
                for (int w = 0; w < 32; ++w) tu += __popc(sh_orw[w]);
                double f2 = sh_mse[row] / tot;
                double f3 = (double)sh_pu[row] / (double)tu;
                sh_cand[row] = (float)((1.0 - f1 / 64.0 + f2 + f3) / 3.0);
            }
        }
        __syncthreads();

        if (tid == 0) {
            float p = 0.f;
            for (int j = 0; j < 64; ++j) p = fmaxf(p, sh_cand[j]);
            g_p = p;
            g_done = 0u;                       // reset for next replay
            const float inv = 1.0f / (1.0f - p);
            for (long long k = (N >> 2) << 2; k < N; ++k)
                out[k] = (noise[k] >= p) ? x[k] * inv : 0.f;
            for (long long k = N; k < out_size; ++k) out[k] = p;
        }
    }
}

// ----------------------------- dropout -------------------------------------
__global__ __launch_bounds__(256)
void dropout_kernel(const float* __restrict__ x, const float* __restrict__ noise,
                    float* __restrict__ out, long long n4) {
    const long long idx = (long long)blockIdx.x * blockDim.x + threadIdx.x;
    const float p   = g_p;
    const float inv = 1.0f / (1.0f - p);
    if (idx < n4) {
        float4 xv = reinterpret_cast<const float4*>(x)[idx];
        float4 nv = __ldcs(reinterpret_cast<const float4*>(noise) + idx);
        float4 o;
        o.x = (nv.x >= p) ? xv.x * inv : 0.f;
        o.y = (nv.y >= p) ? xv.y * inv : 0.f;
        o.z = (nv.z >= p) ? xv.z * inv : 0.f;
        o.w = (nv.w >= p) ? xv.w * inv : 0.f;
        __stcs(reinterpret_cast<float4*>(out) + idx, o);
    }
    // block 0 resets scratch for the next graph replay (initial state = .bss 0)
    if (blockIdx.x == 0) {
        const int t = threadIdx.x;
        for (int i = t; i < 64; i += 256)      g_S[i] = 0.f;
        for (int i = t; i < 64 * 64; i += 256) g_G[i] = 0.f;
        for (int i = t; i < 64 * 32; i += 256) g_maskw[i] = 0u;
    }
}

// ----------------------------- launch --------------------------------------
extern "C" void kernel_launch(void* const* d_in, const int* in_sizes, int n_in,
                              void* d_out, int out_size) {
    const float* x     = (const float*)d_in[0];
    const float* noise = (const float*)d_in[1];
    float* out = (float*)d_out;

    const long long N = (long long)in_sizes[0];
    const int D = (int)(N / 64);
    const int ntiles = D / KTILE;              // 3136 for D = 401408

    cudaFuncSetAttribute(gram_stats_kernel,
                         cudaFuncAttributeMaxDynamicSharedMemorySize, SMEM_BYTES);

    int gblocks = ntiles < 148 ? ntiles : 148; // 1 CTA/SM, 512 threads
    gram_stats_kernel<<<gblocks, 512, SMEM_BYTES>>>(x, noise, out, N,
                                                    (long long)out_size, D, ntiles);

    const long long n4 = N >> 2;
    const int dthreads = 256;
    const unsigned dblocks = (unsigned)((n4 + dthreads - 1) / dthreads);
    dropout_kernel<<<dblocks, dthreads>>>(x, noise, out, n4);
}

// round 10
// speedup vs baseline: 1.0529x; 1.0529x over previous
#include <cuda_runtime.h>
#include <cuda_bf16.h>
#include <cstdint>

// ---------------------------------------------------------------------------
// DifferentialDropout: x [64, D], noise [64, D]  (D = 512*28*28 = 401408)
//   1. gram_stats: 3-stage cp.async ring (16KB f32 tiles, XOR-swizzled),
//      convert -> swizzled bf16 + stats (32-bit round mask), 8 warps x
//      disjoint 16x32 mma tiles, direct REDG. 3 CTAs/SM for issue coverage.
//      Last block runs finalize (factors -> p) in-kernel.
//   2. dropout: out = noise >= p ? x/(1-p) : 0; block 0 re-zeroes scratch
//      for the next graph replay (initial state is .bss-zero).
// ---------------------------------------------------------------------------

static __device__ float        g_S[64];
static __device__ float        g_G[64 * 64];
static __device__ unsigned int g_maskw[64 * 32];   // 1024 bins per row
static __device__ float        g_p;
static __device__ unsigned int g_done;

#define KTILE     64
#define STAGES    3
#define STAGE_U32 4096                       // 16 KB per f32 stage
#define BB_OFF    (STAGES * STAGE_U32)       // u32 offset of bf16 buffers
#define BB_U32    2048                       // 8 KB per bf16 buffer
#define SMEM_BYTES (STAGES * 16384 + 2 * 8192)   // 64 KB per CTA

// bf16 tile: 64 rows x 32 u32 words; 16B chunk c of row r at c ^ (r&7)
__device__ __forceinline__ int swz(int r, int w) {
    return (r << 5) + ((((w >> 2) ^ (r & 7)) << 2) | (w & 3));
}

__device__ __forceinline__ void cp_async16(uint32_t saddr, const void* gptr) {
    asm volatile("cp.async.cg.shared.global [%0], [%1], 16;"
                 :: "r"(saddr), "l"(gptr));
}
__device__ __forceinline__ void cp_commit() {
    asm volatile("cp.async.commit_group;");
}
template <int Nn> __device__ __forceinline__ void cp_wait() {
    asm volatile("cp.async.wait_group %0;" :: "n"(Nn));
}

// ------------------- fused stats + bf16 Gram + finalize --------------------
__global__ __launch_bounds__(256, 3)
void gram_stats_kernel(const float* __restrict__ x,
                       const float* __restrict__ noise,
                       float* __restrict__ out,
                       long long N, long long out_size,
                       int D, int ntiles) {
    extern __shared__ uint32_t dynsmem[];
    float*    fst = reinterpret_cast<float*>(dynsmem);   // 3 x 16KB (swizzled)
    uint32_t* bb  = dynsmem + BB_OFF;                    // 2 x 8KB bf16

    __shared__ int sh_last;

    const int tid  = threadIdx.x;
    const int lane = tid & 31;
    const int warp = tid >> 5;

    // convert mapping: 4 threads/row, 4 float4 each
    const int lrow = tid >> 2;       // 0..63
    const int lc   = tid & 3;        // 0..3
    const int xr   = (lrow & 3) << 2;   // f32-stage chunk swizzle for reads

    // mma mapping: warp -> disjoint 16x32 tile of G
    const int jb = warp >> 2;        // 0..1 -> j0 = jb*32
    const int ib = warp & 3;         // 0..3 -> i0 = ib*16
    const int i0 = ib << 4;
    const int j0 = jb << 5;
    const int lrf = lane & 15;
    const int lch = lane >> 4;

    // cp.async geometry: thread covers rows {j*16 + tid>>4}, fixed col
    const int crow0 = tid >> 4;      // 0..15
    const int ccol  = tid & 15;      // logical 16B chunk in row
    const int pcol  = ccol ^ (((tid >> 4) & 3) << 2);   // physical (swizzled)

    const uint32_t sb_f = (uint32_t)__cvta_generic_to_shared(fst);
    const uint32_t sb_b = (uint32_t)__cvta_generic_to_shared(bb);

    float acc[4][4];
    #pragma unroll
    for (int t = 0; t < 4; ++t)
        #pragma unroll
        for (int r = 0; r < 4; ++r) acc[t][r] = 0.f;

    float    rsum  = 0.f;
    unsigned rmask = 0u;             // bins [-16,15] -> bit b+16

    auto issue = [&](int t, int s) {
        if (t < ntiles) {
            const float* base = x + (size_t)t * KTILE;
            #pragma unroll
            for (int j = 0; j < 4; ++j) {
                const int row = (j << 4) + crow0;
                cp_async16(sb_f + (uint32_t)(s * 16384 + row * 256 + pcol * 16),
                           base + (size_t)row * D + (ccol << 2));
            }
        }
        cp_commit();
    };

    issue(blockIdx.x, 0);
    issue(blockIdx.x + gridDim.x, 1);

    int stage = 0, buf = 0;
    for (int t = blockIdx.x; t < ntiles; t += gridDim.x) {
        cp_wait<STAGES - 2>();
        __syncthreads();             // stage ready; prev-iter readers done

        // refill the slot consumed last iteration (empty S2 at iter 0)
        int s2 = stage + 2; if (s2 >= STAGES) s2 -= STAGES;
        issue(t + 2 * gridDim.x, s2);

        // ---- convert + stats: f32 smem -> bf16 smem ----
        const float* fs   = fst + stage * STAGE_U32 + (lrow << 6);
        uint32_t*    bbuf = bb + buf * BB_U32;
        #pragma unroll
        for (int i = 0; i < 4; ++i) {
            const int j4 = (i << 2) + lc;
            const float4 vv = *reinterpret_cast<const float4*>(fs + ((j4 ^ xr) << 2));
            rsum += (vv.x + vv.y) + (vv.z + vv.w);
            float vals[4] = {vv.x, vv.y, vv.z, vv.w};
            #pragma unroll
            for (int e = 0; e < 4; ++e) {
                int b = __float2int_rn(vals[e]);          // == jnp.round
                unsigned bbn = (unsigned)(b + 16);
                if (bbn < 32u) {
                    rmask |= 1u << bbn;
                } else {                                  // never for N(0,1)
                    int wb = b + 512;
                    wb = wb < 0 ? 0 : (wb > 1023 ? 1023 : wb);
                    atomicOr(&g_maskw[(lrow << 5) + (wb >> 5)], 1u << (wb & 31));
                }
            }
            __nv_bfloat162 p0 = __floats2bfloat162_rn(vv.x, vv.y);
            __nv_bfloat162 p1 = __floats2bfloat162_rn(vv.z, vv.w);
            uint2 pk;
            pk.x = *reinterpret_cast<uint32_t*>(&p0);
            pk.y = *reinterpret_cast<uint32_t*>(&p1);
            *reinterpret_cast<uint2*>(&bbuf[swz(lrow, j4 << 1)]) = pk;
        }
        __syncthreads();             // bf16 tile visible to all warps

        // ---- mma on bbuf: 4 k-steps of 16 ----
        const uint32_t bufb = sb_b + (uint32_t)(buf * 8192);
        #pragma unroll
        for (int ks = 0; ks < 4; ++ks) {
            const int cb = ks << 1;
            uint32_t a[4], bfr[2][4];
            {
                int r = i0 + lrf;
                uint32_t addr = bufb + (uint32_t)((r << 7) + (((cb + lch) ^ (r & 7)) << 4));
                asm volatile("ldmatrix.sync.aligned.m8n8.x4.shared.b16 {%0,%1,%2,%3}, [%4];"
                             : "=r"(a[0]), "=r"(a[1]), "=r"(a[2]), "=r"(a[3])
                             : "r"(addr));
            }
            #pragma unroll
            for (int g = 0; g < 2; ++g) {
                int r = j0 + (g << 4) + lrf;
                uint32_t addr = bufb + (uint32_t)((r << 7) + (((cb + lch) ^ (r & 7)) << 4));
                asm volatile("ldmatrix.sync.aligned.m8n8.x4.shared.b16 {%0,%1,%2,%3}, [%4];"
                             : "=r"(bfr[g][0]), "=r"(bfr[g][1]), "=r"(bfr[g][2]), "=r"(bfr[g][3])
                             : "r"(addr));
            }
            #pragma unroll
            for (int g = 0; g < 2; ++g)
                #pragma unroll
                for (int f = 0; f < 2; ++f) {
                    const int nt = (g << 1) + f;
                    asm volatile("mma.sync.aligned.m16n8k16.row.col.f32.bf16.bf16.f32 "
                                 "{%0,%1,%2,%3}, {%4,%5,%6,%7}, {%8,%9}, {%0,%1,%2,%3};"
                                 : "+f"(acc[nt][0]), "+f"(acc[nt][1]),
                                   "+f"(acc[nt][2]), "+f"(acc[nt][3])
                                 : "r"(a[0]), "r"(a[1]), "r"(a[2]), "r"(a[3]),
                                   "r"(bfr[g][f]), "r"(bfr[g][f + 2]));
                }
        }
        stage = (stage + 1 == STAGES) ? 0 : stage + 1;
        buf ^= 1;
    }
    cp_wait<0>();

    // ---- per-row stats reduce (4 adjacent lanes per row) ----
    rsum += __shfl_xor_sync(0xffffffffu, rsum, 1);
    rsum += __shfl_xor_sync(0xffffffffu, rsum, 2);
    rmask |= __shfl_xor_sync(0xffffffffu, rmask, 1);
    rmask |= __shfl_xor_sync(0xffffffffu, rmask, 2);
    if (lc == 0) {
        atomicAdd(&g_S[lrow], rsum);
        // local bit b+16: b in [-16,-1] -> word15 bits 16..31; b in [0,15] -> word16 bits 0..15
        atomicOr(&g_maskw[(lrow << 5) + 15], (rmask & 0xFFFFu) << 16);
        atomicOr(&g_maskw[(lrow << 5) + 16], rmask >> 16);
    }

    // ---- Gram: disjoint warp tiles -> direct REDG ----
    {
        const int oi = i0 + (lane >> 2);
        #pragma unroll
        for (int nt = 0; nt < 4; ++nt) {
            const int oj = j0 + (nt << 3) + ((lane & 3) << 1);
            atomicAdd(&g_G[oi * 64 + oj],           acc[nt][0]);
            atomicAdd(&g_G[oi * 64 + oj + 1],       acc[nt][1]);
            atomicAdd(&g_G[(oi + 8) * 64 + oj],     acc[nt][2]);
            atomicAdd(&g_G[(oi + 8) * 64 + oj + 1], acc[nt][3]);
        }
    }

    // ---- last block runs finalize ----
    __threadfence();
    __syncthreads();
    if (tid == 0) {
        unsigned v = atomicAdd(&g_done, 1u);
        sh_last = (v == gridDim.x - 1) ? 1 : 0;
    }
    __syncthreads();
    if (!sh_last) return;
    __threadfence();

    {
        __shared__ double       sh_S[64], sh_inv[64], sh_R[64], sh_mse[64];
        __shared__ int          sh_pu[64];
        __shared__ unsigned int sh_orw[32];
        __shared__ float        sh_cand[64];

        const int row = (tid >> 2) & 63;
        const int q   = tid & 3;
        const double Dd     = (double)D;
        const double invD   = 1.0 / Dd;
        const double invDm1 = 1.0 / (Dd - 1.0);

        if (tid < 32) sh_orw[tid] = 0u;
        __syncthreads();

        {
            double R = 0.0;
            #pragma unroll
            for (int j = 0; j < 16; ++j) R += (double)g_G[row * 64 + (q << 4) + j];
            R += __shfl_xor_sync(0xffffffffu, R, 1);
            R += __shfl_xor_sync(0xffffffffu, R, 2);

            int pu = 0;
            #pragma unroll
            for (int w = 0; w < 8; ++w) {
                unsigned m = g_maskw[row * 32 + (q << 3) + w];
                pu += __popc(m);
                atomicOr(&sh_orw[(q << 3) + w], m);
            }
            pu += __shfl_xor_sync(0xffffffffu, pu, 1);
            pu += __shfl_xor_sync(0xffffffffu, pu, 2);

            if (q == 0) {
                sh_R[row]  = R;
                sh_pu[row] = pu;
                sh_S[row]  = (double)g_S[row];
            }
        }
        __syncthreads();

        if (tid < 64) {
            double Si = sh_S[tid];
            double covii = ((double)g_G[tid * 64 + tid] - Si * Si * invD) * invDm1;
            sh_inv[tid] = 1.0 / sqrt(covii);
            double T = 0.0;
            for (int j = 0; j < 64; ++j) T += sh_R[j];
            sh_mse[tid] = ((double)g_G[tid * 64 + tid]
                           - 2.0 * sh_R[tid] / 64.0 + T / 4096.0) * invD;
        }
        __syncthreads();

        {
            const double Si  = sh_S[row];
            const double ivi = sh_inv[row];
            double f1 = 0.0;
            #pragma unroll
            for (int j = 0; j < 16; ++j) {
                const int jj = (q << 4) + j;
                double cov = ((double)g_G[row * 64 + jj] - Si * sh_S[jj] * invD) * invDm1;
                double c = cov * ivi * sh_inv[jj];
                c = fmin(fmax(c, -1.0), 1.0);
                f1 += fabs(c);
            }
            f1 += __shfl_xor_sync(0xffffffffu, f1, 1);
            f1 += __shfl_xor_sync(0xffffffffu, f1, 2);

            if (q == 0) {
                double tot = 0.0;
                for (int j = 0; j < 64; ++j) tot += sh_mse[j];
                int tu = 0;
                for (int w = 0; w < 32; ++w) tu += __popc(sh_orw[w]);
                double f2 = sh_mse[row] / tot;
                double f3 = (double)sh_pu[row] / (double)tu;
                sh_cand[row] = (float)((1.0 - f1 / 64.0 + f2 + f3) / 3.0);
            }
        }
        __syncthreads();

        if (tid == 0) {
            float p = 0.f;
            for (int j = 0; j < 64; ++j) p = fmaxf(p, sh_cand[j]);
            g_p = p;
            g_done = 0u;                       // reset for next replay
            const float inv = 1.0f / (1.0f - p);
            for (long long k = (N >> 2) << 2; k < N; ++k)
                out[k] = (noise[k] >= p) ? x[k] * inv : 0.f;
            for (long long k = N; k < out_size; ++k) out[k] = p;
        }
    }
}

// ----------------------------- dropout -------------------------------------
__global__ __launch_bounds__(256)
void dropout_kernel(const float* __restrict__ x, const float* __restrict__ noise,
                    float* __restrict__ out, long long n4) {
    const long long idx = (long long)blockIdx.x * blockDim.x + threadIdx.x;
    const float p   = g_p;
    const float inv = 1.0f / (1.0f - p);
    if (idx < n4) {
        float4 xv = reinterpret_cast<const float4*>(x)[idx];
        float4 nv = __ldcs(reinterpret_cast<const float4*>(noise) + idx);
        float4 o;
        o.x = (nv.x >= p) ? xv.x * inv : 0.f;
        o.y = (nv.y >= p) ? xv.y * inv : 0.f;
        o.z = (nv.z >= p) ? xv.z * inv : 0.f;
        o.w = (nv.w >= p) ? xv.w * inv : 0.f;
        __stcs(reinterpret_cast<float4*>(out) + idx, o);
    }
    // block 0 resets scratch for the next graph replay (initial state = .bss 0)
    if (blockIdx.x == 0) {
        const int t = threadIdx.x;
        for (int i = t; i < 64; i += 256)      g_S[i] = 0.f;
        for (int i = t; i < 64 * 64; i += 256) g_G[i] = 0.f;
        for (int i = t; i < 64 * 32; i += 256) g_maskw[i] = 0u;
    }
}

// ----------------------------- launch --------------------------------------
extern "C" void kernel_launch(void* const* d_in, const int* in_sizes, int n_in,
                              void* d_out, int out_size) {
    const float* x     = (const float*)d_in[0];
    const float* noise = (const float*)d_in[1];
    float* out = (float*)d_out;

    const long long N = (long long)in_sizes[0];
    const int D = (int)(N / 64);
    const int ntiles = D / KTILE;              // 6272 for D = 401408

    cudaFuncSetAttribute(gram_stats_kernel,
                         cudaFuncAttributeMaxDynamicSharedMemorySize, SMEM_BYTES);

    int gblocks = ntiles < 444 ? ntiles : 444; // 3 CTAs/SM x 148 SMs
    gram_stats_kernel<<<gblocks, 256, SMEM_BYTES>>>(x, noise, out, N,
                                                    (long long)out_size, D, ntiles);

    const long long n4 = N >> 2;
    const int dthreads = 256;
    const unsigned dblocks = (unsigned)((n4 + dthreads - 1) / dthreads);
    dropout_kernel<<<dblocks, dthreads>>>(x, noise, out, n4);
}